// round 13
// baseline (speedup 1.0000x reference)
#include <cuda_runtime.h>
#include <cuda_fp16.h>
#include <math.h>
#include <cstdint>

// Problem constants
#define B_      4
#define T_      2048
#define KDIM    1024
#define HEADS   16
#define HDIM    64
#define ROWS    (B_ * T_)          // 8192
#define HALF    (KDIM / 2)         // 512

// ---------------------------------------------------------------------------
// Scratch (device globals: allocation-free per harness rules)
// ---------------------------------------------------------------------------
__device__ __align__(16) __half g_q[ROWS * KDIM];
__device__ __align__(16) __half g_k[ROWS * KDIM];
__device__ __align__(16) __half g_v[ROWS * KDIM];
__device__ __align__(16) __half g_a[ROWS * KDIM];
__device__ __align__(16) __half g_xt[ROWS * KDIM];
__device__ __align__(16) __half g_wq[KDIM * KDIM];
__device__ __align__(16) __half g_wk[KDIM * KDIM];
__device__ __align__(16) __half g_wv[KDIM * KDIM];
__device__ __align__(16) __half g_wu[KDIM * KDIM];
__device__ __align__(16) float2 g_rope[T_ * HALF];   // cos/sin table (8 MB)

// ---------------------------------------------------------------------------
// Helpers
// ---------------------------------------------------------------------------
__device__ __forceinline__ void mma_f16(float* c, const unsigned* a, const unsigned* b) {
    asm volatile(
        "mma.sync.aligned.m16n8k16.row.col.f32.f16.f16.f32 "
        "{%0,%1,%2,%3}, {%4,%5,%6,%7}, {%8,%9}, {%0,%1,%2,%3};\n"
        : "+f"(c[0]), "+f"(c[1]), "+f"(c[2]), "+f"(c[3])
        : "r"(a[0]), "r"(a[1]), "r"(a[2]), "r"(a[3]), "r"(b[0]), "r"(b[1]));
}

__device__ __forceinline__ void ldsm_x4(unsigned* r, uint32_t addr) {
    asm volatile("ldmatrix.sync.aligned.m8n8.x4.shared.b16 {%0,%1,%2,%3}, [%4];"
        : "=r"(r[0]), "=r"(r[1]), "=r"(r[2]), "=r"(r[3]) : "r"(addr));
}
__device__ __forceinline__ void ldsm_x4_t(unsigned* r, uint32_t addr) {
    asm volatile("ldmatrix.sync.aligned.m8n8.x4.trans.shared.b16 {%0,%1,%2,%3}, [%4];"
        : "=r"(r[0]), "=r"(r[1]), "=r"(r[2]), "=r"(r[3]) : "r"(addr));
}

__device__ __forceinline__ void cp16(void* dst_smem, const void* src) {
    unsigned d = (unsigned)__cvta_generic_to_shared(dst_smem);
    asm volatile("cp.async.cg.shared.global [%0], [%1], 16;\n" :: "r"(d), "l"(src));
}
#define CP_COMMIT() asm volatile("cp.async.commit_group;\n" ::: "memory")
#define CP_WAIT2()  asm volatile("cp.async.wait_group 2;\n" ::: "memory")
#define CP_WAIT3()  asm volatile("cp.async.wait_group 3;\n" ::: "memory")

__device__ __forceinline__ float ex2f(float x) {
    float y;
    asm("ex2.approx.f32 %0, %1;" : "=f"(y) : "f"(x));
    return y;
}
__device__ __forceinline__ unsigned h2ex2(__half2 x) {
    unsigned y;
    asm("ex2.approx.f16x2 %0, %1;" : "=r"(y) : "r"(*(unsigned*)&x));
    return y;
}

#define SOFTMAX_SCALE 0.1803368801111244f   // 0.125 * log2(e)

// ---------------------------------------------------------------------------
// Pre-pass (single launch): z=0 rounds x, z=1..4 round weights,
// z=5 builds the RoPE cos/sin table (same powf/sincosf as before ->
// downstream Q/K values bit-identical).
// ---------------------------------------------------------------------------
__global__ void prepass(const float4* __restrict__ x,
                        const float4* __restrict__ Wq,
                        const float4* __restrict__ Wk,
                        const float4* __restrict__ Wv,
                        const float4* __restrict__ Wu)
{
    const int z = blockIdx.z;
    int i = blockIdx.x * blockDim.x + threadIdx.x;
    if (z == 5) {
        if (i >= T_ * HALF) return;
        int t = i >> 9;              // / HALF
        int j = i & (HALF - 1);
        float theta = powf(10000.0f, -(float)j * (1.0f / (float)HALF));
        float s, c;
        sincosf((float)t * theta, &s, &c);
        g_rope[i] = make_float2(c, s);
        return;
    }
    const float4* in;
    __half2* out;
    int n4;
    if (z == 0)      { in = x;  out = (__half2*)g_xt; n4 = ROWS * KDIM / 4; }
    else if (z == 1) { in = Wq; out = (__half2*)g_wq; n4 = KDIM * KDIM / 4; }
    else if (z == 2) { in = Wk; out = (__half2*)g_wk; n4 = KDIM * KDIM / 4; }
    else if (z == 3) { in = Wv; out = (__half2*)g_wv; n4 = KDIM * KDIM / 4; }
    else             { in = Wu; out = (__half2*)g_wu; n4 = KDIM * KDIM / 4; }
    if (i >= n4) return;
    float4 v = in[i];
    out[2 * i]     = __floats2half2_rn(v.x, v.y);
    out[2 * i + 1] = __floats2half2_rn(v.z, v.w);
}

// ---------------------------------------------------------------------------
// fp16 GEMM core: 128x128x32 CTA tile, 256 threads = 8 warps (2m x 4n),
// warp tile 64x32, 4-stage cp.async pipeline (wait_group 2),
// smem stride 40 halves (ldmatrix conflict-free).
// ---------------------------------------------------------------------------
#define GSH 40
#define GSTGH (2 * 128 * GSH)          // halves per stage (A+B)
#define GSTGB (GSTGH * 2)              // bytes per stage (20480)
#define GSMEM (4 * GSTGB)              // 81920 B

// Fused QKV projection: grid (8, 64, 3).  z selects weight/output/RoPE.
// RoPE via precomputed table; z==0 (Q) also pre-scaled by SOFTMAX_SCALE.
__global__ __launch_bounds__(256, 2) void gemm_qkv()
{
    extern __shared__ __half smh[];
    const uint32_t base_b = (uint32_t)__cvta_generic_to_shared(smh);

    const int z = blockIdx.z;
    const __half* A = g_xt;
    const __half* B = (z == 0) ? g_wq : (z == 1) ? g_wk : g_wv;
    __half* C = (z == 0) ? g_q : (z == 1) ? g_k : g_v;
    const bool do_rope = (z < 2);

    const int tid  = threadIdx.x;
    const int lane = tid & 31;
    const int warp = tid >> 5;
    const int g = lane >> 2;
    const int t = lane & 3;
    const int wm = warp >> 2;
    const int wn = warp & 3;
    const int bm = blockIdx.y * 128;
    const int bn = blockIdx.x * 128;

    float c[4][4][4];
#pragma unroll
    for (int i = 0; i < 4; i++)
#pragma unroll
        for (int j = 0; j < 4; j++)
#pragma unroll
            for (int e = 0; e < 4; e++) c[i][j][e] = 0.0f;

    const int lrow = tid >> 1;
    const int lcb  = (tid & 1) * 16;
    const __half* Ap = A + (size_t)(bm + lrow) * KDIM + lcb;
    const __half* Bp = B + (size_t)(bn + lrow) * KDIM + lcb;

    auto fill = [&](int ch, int s) {
        __half* Asd = smh + s * GSTGH + lrow * GSH + lcb;
        __half* Bsd = Asd + 128 * GSH;
        cp16(Asd, Ap + ch * 32); cp16(Asd + 8, Ap + ch * 32 + 8);
        cp16(Bsd, Bp + ch * 32); cp16(Bsd + 8, Bp + ch * 32 + 8);
    };

    fill(0, 0); CP_COMMIT();
    fill(1, 1); CP_COMMIT();
    fill(2, 2); CP_COMMIT();

    const int a_row = wm * 64 + (lane & 15);
    const int a_colh = (lane >> 4) << 3;
    const int b_row = wn * 32 + ((lane >> 4) << 3) + (lane & 7);
    const int b_colh = ((lane >> 3) & 1) << 3;

    const int NCH = KDIM / 32;           // 32
    for (int i = 0; i < NCH; i++) {
        const int s = i & 3;
        CP_WAIT2();
        __syncthreads();
        const int j = i + 3;
        if (j < NCH) fill(j, j & 3);
        CP_COMMIT();

        const uint32_t Ab = base_b + s * GSTGB;
        const uint32_t Bb = Ab + 128 * GSH * 2;
#pragma unroll
        for (int ks = 0; ks < 2; ks++) {
            unsigned a[4][4], bf[4][2];
#pragma unroll
            for (int mt = 0; mt < 4; mt++)
                ldsm_x4(a[mt], Ab + ((a_row + mt * 16) * GSH + 16 * ks + a_colh) * 2);
#pragma unroll
            for (int ntp = 0; ntp < 2; ntp++) {
                unsigned r[4];
                ldsm_x4(r, Bb + ((b_row + ntp * 16) * GSH + 16 * ks + b_colh) * 2);
                bf[2 * ntp][0] = r[0]; bf[2 * ntp][1] = r[1];
                bf[2 * ntp + 1][0] = r[2]; bf[2 * ntp + 1][1] = r[3];
            }
#pragma unroll
            for (int mt = 0; mt < 4; mt++)
#pragma unroll
                for (int nt = 0; nt < 4; nt++)
                    mma_f16(c[mt][nt], a[mt], bf[nt]);
        }
    }

    // Epilogue: RoPE via table (z<2), Q pre-scaled; fp16 store
#pragma unroll
    for (int mt = 0; mt < 4; mt++) {
        int row = bm + wm * 64 + mt * 16 + g;
        int t0 = row & (T_ - 1);
#pragma unroll
        for (int nt = 0; nt < 4; nt++) {
            int col = bn + wn * 32 + nt * 8 + 2 * t;
            float v0x = c[mt][nt][0], v0y = c[mt][nt][1];
            float v1x = c[mt][nt][2], v1y = c[mt][nt][3];
            if (do_rope) {
                int j = col >> 1;
                float2 cs0 = g_rope[t0 * HALF + j];
                float2 cs1 = g_rope[(t0 + 8) * HALF + j];
                float r0x = v0x * cs0.x - v0y * cs0.y;
                float r0y = v0x * cs0.y + v0y * cs0.x;
                float r1x = v1x * cs1.x - v1y * cs1.y;
                float r1y = v1x * cs1.y + v1y * cs1.x;
                v0x = r0x; v0y = r0y; v1x = r1x; v1y = r1y;
                if (z == 0) {
                    v0x *= SOFTMAX_SCALE; v0y *= SOFTMAX_SCALE;
                    v1x *= SOFTMAX_SCALE; v1y *= SOFTMAX_SCALE;
                }
            }
            *(__half2*)&C[(size_t)row * KDIM + col] = __floats2half2_rn(v0x, v0y);
            *(__half2*)&C[(size_t)(row + 8) * KDIM + col] = __floats2half2_rn(v1x, v1y);
        }
    }
}

// Output projection: fp32 store + bias
__global__ __launch_bounds__(256, 2) void gemm_out(
    const float* __restrict__ bias, float* __restrict__ C)
{
    extern __shared__ __half smh[];
    const uint32_t base_b = (uint32_t)__cvta_generic_to_shared(smh);

    const int tid  = threadIdx.x;
    const int lane = tid & 31;
    const int warp = tid >> 5;
    const int g = lane >> 2;
    const int t = lane & 3;
    const int wm = warp >> 2;
    const int wn = warp & 3;
    const int bm = blockIdx.y * 128;
    const int bn = blockIdx.x * 128;

    float c[4][4][4];
#pragma unroll
    for (int i = 0; i < 4; i++)
#pragma unroll
        for (int j = 0; j < 4; j++)
#pragma unroll
            for (int e = 0; e < 4; e++) c[i][j][e] = 0.0f;

    const int lrow = tid >> 1;
    const int lcb  = (tid & 1) * 16;
    const __half* Ap = g_a  + (size_t)(bm + lrow) * KDIM + lcb;
    const __half* Bp = g_wu + (size_t)(bn + lrow) * KDIM + lcb;

    auto fill = [&](int ch, int s) {
        __half* Asd = smh + s * GSTGH + lrow * GSH + lcb;
        __half* Bsd = Asd + 128 * GSH;
        cp16(Asd, Ap + ch * 32); cp16(Asd + 8, Ap + ch * 32 + 8);
        cp16(Bsd, Bp + ch * 32); cp16(Bsd + 8, Bp + ch * 32 + 8);
    };

    fill(0, 0); CP_COMMIT();
    fill(1, 1); CP_COMMIT();
    fill(2, 2); CP_COMMIT();

    const int a_row = wm * 64 + (lane & 15);
    const int a_colh = (lane >> 4) << 3;
    const int b_row = wn * 32 + ((lane >> 4) << 3) + (lane & 7);
    const int b_colh = ((lane >> 3) & 1) << 3;

    const int NCH = KDIM / 32;
    for (int i = 0; i < NCH; i++) {
        const int s = i & 3;
        CP_WAIT2();
        __syncthreads();
        const int j = i + 3;
        if (j < NCH) fill(j, j & 3);
        CP_COMMIT();

        const uint32_t Ab = base_b + s * GSTGB;
        const uint32_t Bb = Ab + 128 * GSH * 2;
#pragma unroll
        for (int ks = 0; ks < 2; ks++) {
            unsigned a[4][4], bf[4][2];
#pragma unroll
            for (int mt = 0; mt < 4; mt++)
                ldsm_x4(a[mt], Ab + ((a_row + mt * 16) * GSH + 16 * ks + a_colh) * 2);
#pragma unroll
            for (int ntp = 0; ntp < 2; ntp++) {
                unsigned r[4];
                ldsm_x4(r, Bb + ((b_row + ntp * 16) * GSH + 16 * ks + b_colh) * 2);
                bf[2 * ntp][0] = r[0]; bf[2 * ntp][1] = r[1];
                bf[2 * ntp + 1][0] = r[2]; bf[2 * ntp + 1][1] = r[3];
            }
#pragma unroll
            for (int mt = 0; mt < 4; mt++)
#pragma unroll
                for (int nt = 0; nt < 4; nt++)
                    mma_f16(c[mt][nt], a[mt], bf[nt]);
        }
    }

#pragma unroll
    for (int mt = 0; mt < 4; mt++) {
        int row = bm + wm * 64 + mt * 16 + g;
#pragma unroll
        for (int nt = 0; nt < 4; nt++) {
            int col = bn + wn * 32 + nt * 8 + 2 * t;
            float bx = bias[col], by = bias[col + 1];
            *(float2*)&C[(size_t)row * KDIM + col] =
                make_float2(c[mt][nt][0] + bx, c[mt][nt][1] + by);
            *(float2*)&C[(size_t)(row + 8) * KDIM + col] =
                make_float2(c[mt][nt][2] + bx, c[mt][nt][3] + by);
        }
    }
}

// ---------------------------------------------------------------------------
// Flash attention, fp16 mma m16n8k16, 4-stage K/V cp.async pipeline.
// CTA = 128 q-rows x (batch*head), *** 4 warps x 32 q-rows *** (128 thr):
// each warp's K/V fragments feed TWO 16-row m-tiles -> crossbar traffic
// per CTA halves vs 8x16.  128-thr CTA allows ~250 regs at 2 CTA/SM.
// Q fragments hoisted; Q pre-scaled by 0.125*log2e; ex2.approx.f16x2 P;
// warp-uniform corr-skip.
// ---------------------------------------------------------------------------
#define QSTR 72
#define KSTR 72
#define VSTR 72
#define QSZ  (128 * QSTR)              // halves
#define SSZ  (64 * KSTR + 64 * VSTR)   // halves per K/V stage

__global__ __launch_bounds__(128, 2) void attn_f16(
    const __half* __restrict__ Q, const __half* __restrict__ K,
    const __half* __restrict__ V, __half* __restrict__ O)
{
    extern __shared__ __half smh[];
    __half* Qs = smh;
    __half* KV = smh + QSZ;            // 4 stages of [K(64xKSTR) | V(64xVSTR)]
    const uint32_t Qs_b = (uint32_t)__cvta_generic_to_shared(Qs);
    const uint32_t KV_b = (uint32_t)__cvta_generic_to_shared(KV);

    const int tid  = threadIdx.x;
    const int lane = tid & 31;
    const int warp = tid >> 5;          // 0..3
    const int g = lane >> 2;
    const int t = lane & 3;
    const int wrow = warp * 32;

    const int qtile = blockIdx.x;
    const int bh = blockIdx.y;
    const int b = bh >> 4;
    const int h = bh & 15;
    const size_t rowbase = (size_t)b * T_;
    const int colbase = h * HDIM;

    // K/V loader: 2 threads per row, 32 halves each
    const int lrow2 = tid >> 1;         // 0..63
    const int lcb2  = (tid & 1) * 32;

    auto fill_kv = [&](int kt, int s) {
        const size_t gb = (rowbase + kt * 64 + lrow2) * KDIM + colbase + lcb2;
        __half* kd = KV + s * SSZ + lrow2 * KSTR + lcb2;
        __half* vd = kd + 64 * KSTR;
        cp16(kd, K + gb); cp16(kd + 8, K + gb + 8);
        cp16(kd + 16, K + gb + 16); cp16(kd + 24, K + gb + 24);
        cp16(vd, V + gb); cp16(vd + 8, V + gb + 8);
        cp16(vd + 16, V + gb + 16); cp16(vd + 24, V + gb + 24);
    };

    // ---- Stage Q tile [128 x 64]: one row per thread
    {
        const __half* src = Q + (rowbase + qtile * 128 + tid) * KDIM + colbase;
        __half* dst = Qs + tid * QSTR;
#pragma unroll
        for (int i = 0; i < 8; i++) cp16(dst + 8 * i, src + 8 * i);
        CP_COMMIT();
    }
    fill_kv(0, 0); CP_COMMIT();
    fill_kv(1, 1); CP_COMMIT();
    fill_kv(2, 2); CP_COMMIT();

    // ---- Hoist Q fragments for both m-tiles
    const int qa_colh = (lane >> 4) << 3;
    unsigned qf[2][4][4];
    CP_WAIT3();
    __syncthreads();
#pragma unroll
    for (int mt2 = 0; mt2 < 2; mt2++) {
        const int qa_row = wrow + mt2 * 16 + (lane & 15);
#pragma unroll
        for (int ds = 0; ds < 4; ds++)
            ldsm_x4(qf[mt2][ds], Qs_b + (qa_row * QSTR + 16 * ds + qa_colh) * 2);
    }

    float m[2][2], l[2][2];
#pragma unroll
    for (int mt2 = 0; mt2 < 2; mt2++) {
        m[mt2][0] = -1e30f; m[mt2][1] = -1e30f;
        l[mt2][0] = 0.0f;   l[mt2][1] = 0.0f;
    }
    float o[2][8][4];
#pragma unroll
    for (int mt2 = 0; mt2 < 2; mt2++)
#pragma unroll
        for (int j = 0; j < 8; j++)
#pragma unroll
            for (int e = 0; e < 4; e++) o[mt2][j][e] = 0.0f;

    const int kb_row = ((lane >> 4) << 3) + (lane & 7);
    const int kb_colh = ((lane >> 3) & 1) << 3;
    const int vb_row = (((lane >> 3) & 1) << 3) + (lane & 7);
    const int vb_colh = (lane >> 4) << 3;

    const int NT = T_ / 64;              // 32
    for (int kt = 0; kt < NT; kt++) {
        const int s = kt & 3;
        const uint32_t Kb = KV_b + s * SSZ * 2;
        const uint32_t Vb = Kb + 64 * KSTR * 2;

        CP_WAIT2();
        __syncthreads();
        const int jn = kt + 3;
        if (jn < NT) fill_kv(jn, jn & 3);
        CP_COMMIT();

        // ---- S = Q K^T (warp tile 32 x 64): K frags shared by both m-tiles
        float sc[2][8][4];
#pragma unroll
        for (int mt2 = 0; mt2 < 2; mt2++)
#pragma unroll
            for (int j = 0; j < 8; j++)
#pragma unroll
                for (int e = 0; e < 4; e++) sc[mt2][j][e] = 0.0f;

#pragma unroll
        for (int ds = 0; ds < 4; ds++) {
#pragma unroll
            for (int jj = 0; jj < 4; jj++) {
                unsigned r[4];
                ldsm_x4(r, Kb + ((16 * jj + kb_row) * KSTR + 16 * ds + kb_colh) * 2);
                mma_f16(sc[0][2 * jj], qf[0][ds], r);
                mma_f16(sc[0][2 * jj + 1], qf[0][ds], r + 2);
                mma_f16(sc[1][2 * jj], qf[1][ds], r);
                mma_f16(sc[1][2 * jj + 1], qf[1][ds], r + 2);
            }
        }

        // ---- Online softmax per m-tile; P packed via f16x2 ex2
        unsigned pf[2][4][4];
        bool nochange = true;
#pragma unroll
        for (int mt2 = 0; mt2 < 2; mt2++) {
            float mx0 = -1e30f, mx1 = -1e30f;
#pragma unroll
            for (int j = 0; j < 8; j++) {
                mx0 = fmaxf(mx0, fmaxf(sc[mt2][j][0], sc[mt2][j][1]));
                mx1 = fmaxf(mx1, fmaxf(sc[mt2][j][2], sc[mt2][j][3]));
            }
            mx0 = fmaxf(mx0, __shfl_xor_sync(0xffffffffu, mx0, 1));
            mx0 = fmaxf(mx0, __shfl_xor_sync(0xffffffffu, mx0, 2));
            mx1 = fmaxf(mx1, __shfl_xor_sync(0xffffffffu, mx1, 1));
            mx1 = fmaxf(mx1, __shfl_xor_sync(0xffffffffu, mx1, 2));

            float mn0 = fmaxf(m[mt2][0], mx0);
            float mn1 = fmaxf(m[mt2][1], mx1);

            float rs0 = 0.0f, rs1 = 0.0f;
#pragma unroll
            for (int j = 0; j < 8; j++) {
                unsigned h01 = h2ex2(__floats2half2_rn(sc[mt2][j][0] - mn0,
                                                       sc[mt2][j][1] - mn0));
                unsigned h23 = h2ex2(__floats2half2_rn(sc[mt2][j][2] - mn1,
                                                       sc[mt2][j][3] - mn1));
                float2 f01 = __half22float2(*(__half2*)&h01);
                float2 f23 = __half22float2(*(__half2*)&h23);
                rs0 += f01.x + f01.y;
                rs1 += f23.x + f23.y;
                pf[mt2][j >> 1][((j & 1) << 1) + 0] = h01;
                pf[mt2][j >> 1][((j & 1) << 1) + 1] = h23;
            }
            rs0 += __shfl_xor_sync(0xffffffffu, rs0, 1);
            rs0 += __shfl_xor_sync(0xffffffffu, rs0, 2);
            rs1 += __shfl_xor_sync(0xffffffffu, rs1, 1);
            rs1 += __shfl_xor_sync(0xffffffffu, rs1, 2);

            bool nc = (mn0 == m[mt2][0]) && (mn1 == m[mt2][1]);
            nochange = nochange && nc;
            if (nc) {
                l[mt2][0] += rs0;
                l[mt2][1] += rs1;
            } else {
                float corr0 = ex2f(m[mt2][0] - mn0);
                float corr1 = ex2f(m[mt2][1] - mn1);
                l[mt2][0] = l[mt2][0] * corr0 + rs0;
                l[mt2][1] = l[mt2][1] * corr1 + rs1;
#pragma unroll
                for (int j = 0; j < 8; j++) {
                    o[mt2][j][0] *= corr0; o[mt2][j][1] *= corr0;
                    o[mt2][j][2] *= corr1; o[mt2][j][3] *= corr1;
                }
                m[mt2][0] = mn0; m[mt2][1] = mn1;
            }
        }
        (void)nochange;

        // ---- O += P V : V frags shared by both m-tiles
#pragma unroll
        for (int s2 = 0; s2 < 4; s2++) {
#pragma unroll
            for (int jj2 = 0; jj2 < 4; jj2++) {
                unsigned r[4];
                ldsm_x4_t(r, Vb + ((16 * s2 + vb_row) * VSTR + 16 * jj2 + vb_colh) * 2);
                mma_f16(o[0][2 * jj2], pf[0][s2], r);
                mma_f16(o[0][2 * jj2 + 1], pf[0][s2], r + 2);
                mma_f16(o[1][2 * jj2], pf[1][s2], r);
                mma_f16(o[1][2 * jj2 + 1], pf[1][s2], r + 2);
            }
        }
    }

    // ---- Normalize, store fp16 ([b*t][h*64])
#pragma unroll
    for (int mt2 = 0; mt2 < 2; mt2++) {
        float inv0 = 1.0f / l[mt2][0];
        float inv1 = 1.0f / l[mt2][1];
        size_t orow0 = (rowbase + qtile * 128 + wrow + mt2 * 16 + g) * KDIM + colbase;
        size_t orow1 = orow0 + (size_t)8 * KDIM;
#pragma unroll
        for (int j = 0; j < 8; j++) {
            int col = 8 * j + 2 * t;
            *(__half2*)&O[orow0 + col] =
                __floats2half2_rn(o[mt2][j][0] * inv0, o[mt2][j][1] * inv0);
            *(__half2*)&O[orow1 + col] =
                __floats2half2_rn(o[mt2][j][2] * inv1, o[mt2][j][3] * inv1);
        }
    }
}

// ---------------------------------------------------------------------------
// Launcher
// ---------------------------------------------------------------------------
extern "C" void kernel_launch(void* const* d_in, const int* in_sizes, int n_in,
                              void* d_out, int out_size)
{
    const float* x  = (const float*)d_in[0];
    const float* Wq = (const float*)d_in[1];
    const float* Wk = (const float*)d_in[2];
    const float* Wv = (const float*)d_in[3];
    const float* Wu = (const float*)d_in[4];
    const float* bu = (const float*)d_in[5];
    float* out = (float*)d_out;

    __half *q, *k, *v, *a;
    cudaGetSymbolAddress((void**)&q, g_q);
    cudaGetSymbolAddress((void**)&k, g_k);
    cudaGetSymbolAddress((void**)&v, g_v);
    cudaGetSymbolAddress((void**)&a, g_a);

    // Pre-pass: rounds x + weights, builds RoPE table (z=5)
    {
        int blocks_x = (ROWS * KDIM / 4 + 255) / 256;   // 8192 (covers all z)
        prepass<<<dim3(blocks_x, 1, 6), 256>>>(
            (const float4*)x, (const float4*)Wq, (const float4*)Wk,
            (const float4*)Wv, (const float4*)Wu);
    }

    cudaFuncSetAttribute(gemm_qkv, cudaFuncAttributeMaxDynamicSharedMemorySize, GSMEM);
    cudaFuncSetAttribute(gemm_out, cudaFuncAttributeMaxDynamicSharedMemorySize, GSMEM);

    // Fused QKV projections (one launch, grid.z selects Q/K/V)
    gemm_qkv<<<dim3(KDIM / 128, ROWS / 128, 3), 256, GSMEM>>>();

    // Attention: 128 q-rows per CTA, 4 warps x 32 rows
    const int attn_smem = (QSZ + 4 * SSZ) * (int)sizeof(__half);  // 92160 B
    cudaFuncSetAttribute(attn_f16, cudaFuncAttributeMaxDynamicSharedMemorySize, attn_smem);
    attn_f16<<<dim3(T_ / 128, B_ * HEADS), 128, attn_smem>>>(q, k, v, a);

    // Output projection + bias (fp32 store)
    gemm_out<<<dim3(KDIM / 128, ROWS / 128), 256, GSMEM>>>(bu, out);
}

// round 14
// speedup vs baseline: 1.0342x; 1.0342x over previous
#include <cuda_runtime.h>
#include <cuda_fp16.h>
#include <math.h>
#include <cstdint>

// Problem constants
#define B_      4
#define T_      2048
#define KDIM    1024
#define HEADS   16
#define HDIM    64
#define ROWS    (B_ * T_)          // 8192
#define HALF    (KDIM / 2)         // 512

// ---------------------------------------------------------------------------
// Scratch (device globals: allocation-free per harness rules)
// ---------------------------------------------------------------------------
__device__ __align__(16) __half g_q[ROWS * KDIM];
__device__ __align__(16) __half g_k[ROWS * KDIM];
__device__ __align__(16) __half g_v[ROWS * KDIM];
__device__ __align__(16) __half g_a[ROWS * KDIM];
__device__ __align__(16) __half g_xt[ROWS * KDIM];
__device__ __align__(16) __half g_wq[KDIM * KDIM];
__device__ __align__(16) __half g_wk[KDIM * KDIM];
__device__ __align__(16) __half g_wv[KDIM * KDIM];
__device__ __align__(16) __half g_wu[KDIM * KDIM];
__device__ __align__(16) float2 g_rope[T_ * HALF];   // cos/sin table (8 MB)

// ---------------------------------------------------------------------------
// Helpers
// ---------------------------------------------------------------------------
__device__ __forceinline__ void mma_f16(float* c, const unsigned* a, const unsigned* b) {
    asm volatile(
        "mma.sync.aligned.m16n8k16.row.col.f32.f16.f16.f32 "
        "{%0,%1,%2,%3}, {%4,%5,%6,%7}, {%8,%9}, {%0,%1,%2,%3};\n"
        : "+f"(c[0]), "+f"(c[1]), "+f"(c[2]), "+f"(c[3])
        : "r"(a[0]), "r"(a[1]), "r"(a[2]), "r"(a[3]), "r"(b[0]), "r"(b[1]));
}

__device__ __forceinline__ void ldsm_x4(unsigned* r, uint32_t addr) {
    asm volatile("ldmatrix.sync.aligned.m8n8.x4.shared.b16 {%0,%1,%2,%3}, [%4];"
        : "=r"(r[0]), "=r"(r[1]), "=r"(r[2]), "=r"(r[3]) : "r"(addr));
}
__device__ __forceinline__ void ldsm_x4_t(unsigned* r, uint32_t addr) {
    asm volatile("ldmatrix.sync.aligned.m8n8.x4.trans.shared.b16 {%0,%1,%2,%3}, [%4];"
        : "=r"(r[0]), "=r"(r[1]), "=r"(r[2]), "=r"(r[3]) : "r"(addr));
}

__device__ __forceinline__ void cp16(void* dst_smem, const void* src) {
    unsigned d = (unsigned)__cvta_generic_to_shared(dst_smem);
    asm volatile("cp.async.cg.shared.global [%0], [%1], 16;\n" :: "r"(d), "l"(src));
}
#define CP_COMMIT() asm volatile("cp.async.commit_group;\n" ::: "memory")
#define CP_WAIT2()  asm volatile("cp.async.wait_group 2;\n" ::: "memory")
#define CP_WAIT3()  asm volatile("cp.async.wait_group 3;\n" ::: "memory")

__device__ __forceinline__ float ex2f(float x) {
    float y;
    asm("ex2.approx.f32 %0, %1;" : "=f"(y) : "f"(x));
    return y;
}
__device__ __forceinline__ unsigned h2ex2(__half2 x) {
    unsigned y;
    asm("ex2.approx.f16x2 %0, %1;" : "=r"(y) : "r"(*(unsigned*)&x));
    return y;
}

#define SOFTMAX_SCALE 0.1803368801111244f   // 0.125 * log2(e)

// ---------------------------------------------------------------------------
// Pre-pass (single launch): z=0 rounds x, z=1..4 round weights,
// z=5 builds the RoPE cos/sin table (same powf/sincosf sequence as the old
// inline epilogue -> downstream Q/K bit-identical).
// ---------------------------------------------------------------------------
__global__ void prepass(const float4* __restrict__ x,
                        const float4* __restrict__ Wq,
                        const float4* __restrict__ Wk,
                        const float4* __restrict__ Wv,
                        const float4* __restrict__ Wu)
{
    const int z = blockIdx.z;
    int i = blockIdx.x * blockDim.x + threadIdx.x;
    if (z == 5) {
        if (i >= T_ * HALF) return;
        int t = i >> 9;              // / HALF
        int j = i & (HALF - 1);
        float theta = powf(10000.0f, -(float)j * (1.0f / (float)HALF));
        float s, c;
        sincosf((float)t * theta, &s, &c);
        g_rope[i] = make_float2(c, s);
        return;
    }
    const float4* in;
    __half2* out;
    int n4;
    if (z == 0)      { in = x;  out = (__half2*)g_xt; n4 = ROWS * KDIM / 4; }
    else if (z == 1) { in = Wq; out = (__half2*)g_wq; n4 = KDIM * KDIM / 4; }
    else if (z == 2) { in = Wk; out = (__half2*)g_wk; n4 = KDIM * KDIM / 4; }
    else if (z == 3) { in = Wv; out = (__half2*)g_wv; n4 = KDIM * KDIM / 4; }
    else             { in = Wu; out = (__half2*)g_wu; n4 = KDIM * KDIM / 4; }
    if (i >= n4) return;
    float4 v = in[i];
    out[2 * i]     = __floats2half2_rn(v.x, v.y);
    out[2 * i + 1] = __floats2half2_rn(v.z, v.w);
}

// ---------------------------------------------------------------------------
// fp16 GEMM core: 128x128x32 CTA tile, 256 threads = 8 warps (2m x 4n),
// warp tile 64x32, 4-stage cp.async pipeline (wait_group 2),
// smem stride 40 halves (ldmatrix conflict-free).
// ---------------------------------------------------------------------------
#define GSH 40
#define GSTGH (2 * 128 * GSH)          // halves per stage (A+B)
#define GSTGB (GSTGH * 2)              // bytes per stage (20480)
#define GSMEM (4 * GSTGB)              // 81920 B

// Fused QKV projection: grid (8, 64, 3).  z selects weight/output/RoPE.
// RoPE via precomputed table; z==0 (Q) also pre-scaled by SOFTMAX_SCALE.
__global__ __launch_bounds__(256, 2) void gemm_qkv()
{
    extern __shared__ __half smh[];
    const uint32_t base_b = (uint32_t)__cvta_generic_to_shared(smh);

    const int z = blockIdx.z;
    const __half* A = g_xt;
    const __half* B = (z == 0) ? g_wq : (z == 1) ? g_wk : g_wv;
    __half* C = (z == 0) ? g_q : (z == 1) ? g_k : g_v;
    const bool do_rope = (z < 2);

    const int tid  = threadIdx.x;
    const int lane = tid & 31;
    const int warp = tid >> 5;
    const int g = lane >> 2;
    const int t = lane & 3;
    const int wm = warp >> 2;
    const int wn = warp & 3;
    const int bm = blockIdx.y * 128;
    const int bn = blockIdx.x * 128;

    float c[4][4][4];
#pragma unroll
    for (int i = 0; i < 4; i++)
#pragma unroll
        for (int j = 0; j < 4; j++)
#pragma unroll
            for (int e = 0; e < 4; e++) c[i][j][e] = 0.0f;

    const int lrow = tid >> 1;
    const int lcb  = (tid & 1) * 16;
    const __half* Ap = A + (size_t)(bm + lrow) * KDIM + lcb;
    const __half* Bp = B + (size_t)(bn + lrow) * KDIM + lcb;

    auto fill = [&](int ch, int s) {
        __half* Asd = smh + s * GSTGH + lrow * GSH + lcb;
        __half* Bsd = Asd + 128 * GSH;
        cp16(Asd, Ap + ch * 32); cp16(Asd + 8, Ap + ch * 32 + 8);
        cp16(Bsd, Bp + ch * 32); cp16(Bsd + 8, Bp + ch * 32 + 8);
    };

    fill(0, 0); CP_COMMIT();
    fill(1, 1); CP_COMMIT();
    fill(2, 2); CP_COMMIT();

    const int a_row = wm * 64 + (lane & 15);
    const int a_colh = (lane >> 4) << 3;
    const int b_row = wn * 32 + ((lane >> 4) << 3) + (lane & 7);
    const int b_colh = ((lane >> 3) & 1) << 3;

    const int NCH = KDIM / 32;           // 32
    for (int i = 0; i < NCH; i++) {
        const int s = i & 3;
        CP_WAIT2();
        __syncthreads();
        const int j = i + 3;
        if (j < NCH) fill(j, j & 3);
        CP_COMMIT();

        const uint32_t Ab = base_b + s * GSTGB;
        const uint32_t Bb = Ab + 128 * GSH * 2;
#pragma unroll
        for (int ks = 0; ks < 2; ks++) {
            unsigned a[4][4], bf[4][2];
#pragma unroll
            for (int mt = 0; mt < 4; mt++)
                ldsm_x4(a[mt], Ab + ((a_row + mt * 16) * GSH + 16 * ks + a_colh) * 2);
#pragma unroll
            for (int ntp = 0; ntp < 2; ntp++) {
                unsigned r[4];
                ldsm_x4(r, Bb + ((b_row + ntp * 16) * GSH + 16 * ks + b_colh) * 2);
                bf[2 * ntp][0] = r[0]; bf[2 * ntp][1] = r[1];
                bf[2 * ntp + 1][0] = r[2]; bf[2 * ntp + 1][1] = r[3];
            }
#pragma unroll
            for (int mt = 0; mt < 4; mt++)
#pragma unroll
                for (int nt = 0; nt < 4; nt++)
                    mma_f16(c[mt][nt], a[mt], bf[nt]);
        }
    }

    // Epilogue: RoPE via table (z<2), Q pre-scaled; fp16 store
#pragma unroll
    for (int mt = 0; mt < 4; mt++) {
        int row = bm + wm * 64 + mt * 16 + g;
        int t0 = row & (T_ - 1);
#pragma unroll
        for (int nt = 0; nt < 4; nt++) {
            int col = bn + wn * 32 + nt * 8 + 2 * t;
            float v0x = c[mt][nt][0], v0y = c[mt][nt][1];
            float v1x = c[mt][nt][2], v1y = c[mt][nt][3];
            if (do_rope) {
                int j = col >> 1;
                float2 cs0 = g_rope[t0 * HALF + j];
                float2 cs1 = g_rope[(t0 + 8) * HALF + j];
                float r0x = v0x * cs0.x - v0y * cs0.y;
                float r0y = v0x * cs0.y + v0y * cs0.x;
                float r1x = v1x * cs1.x - v1y * cs1.y;
                float r1y = v1x * cs1.y + v1y * cs1.x;
                v0x = r0x; v0y = r0y; v1x = r1x; v1y = r1y;
                if (z == 0) {
                    v0x *= SOFTMAX_SCALE; v0y *= SOFTMAX_SCALE;
                    v1x *= SOFTMAX_SCALE; v1y *= SOFTMAX_SCALE;
                }
            }
            *(__half2*)&C[(size_t)row * KDIM + col] = __floats2half2_rn(v0x, v0y);
            *(__half2*)&C[(size_t)(row + 8) * KDIM + col] = __floats2half2_rn(v1x, v1y);
        }
    }
}

// Output projection: fp32 store + bias
__global__ __launch_bounds__(256, 2) void gemm_out(
    const float* __restrict__ bias, float* __restrict__ C)
{
    extern __shared__ __half smh[];
    const uint32_t base_b = (uint32_t)__cvta_generic_to_shared(smh);

    const int tid  = threadIdx.x;
    const int lane = tid & 31;
    const int warp = tid >> 5;
    const int g = lane >> 2;
    const int t = lane & 3;
    const int wm = warp >> 2;
    const int wn = warp & 3;
    const int bm = blockIdx.y * 128;
    const int bn = blockIdx.x * 128;

    float c[4][4][4];
#pragma unroll
    for (int i = 0; i < 4; i++)
#pragma unroll
        for (int j = 0; j < 4; j++)
#pragma unroll
            for (int e = 0; e < 4; e++) c[i][j][e] = 0.0f;

    const int lrow = tid >> 1;
    const int lcb  = (tid & 1) * 16;
    const __half* Ap = g_a  + (size_t)(bm + lrow) * KDIM + lcb;
    const __half* Bp = g_wu + (size_t)(bn + lrow) * KDIM + lcb;

    auto fill = [&](int ch, int s) {
        __half* Asd = smh + s * GSTGH + lrow * GSH + lcb;
        __half* Bsd = Asd + 128 * GSH;
        cp16(Asd, Ap + ch * 32); cp16(Asd + 8, Ap + ch * 32 + 8);
        cp16(Bsd, Bp + ch * 32); cp16(Bsd + 8, Bp + ch * 32 + 8);
    };

    fill(0, 0); CP_COMMIT();
    fill(1, 1); CP_COMMIT();
    fill(2, 2); CP_COMMIT();

    const int a_row = wm * 64 + (lane & 15);
    const int a_colh = (lane >> 4) << 3;
    const int b_row = wn * 32 + ((lane >> 4) << 3) + (lane & 7);
    const int b_colh = ((lane >> 3) & 1) << 3;

    const int NCH = KDIM / 32;
    for (int i = 0; i < NCH; i++) {
        const int s = i & 3;
        CP_WAIT2();
        __syncthreads();
        const int j = i + 3;
        if (j < NCH) fill(j, j & 3);
        CP_COMMIT();

        const uint32_t Ab = base_b + s * GSTGB;
        const uint32_t Bb = Ab + 128 * GSH * 2;
#pragma unroll
        for (int ks = 0; ks < 2; ks++) {
            unsigned a[4][4], bf[4][2];
#pragma unroll
            for (int mt = 0; mt < 4; mt++)
                ldsm_x4(a[mt], Ab + ((a_row + mt * 16) * GSH + 16 * ks + a_colh) * 2);
#pragma unroll
            for (int ntp = 0; ntp < 2; ntp++) {
                unsigned r[4];
                ldsm_x4(r, Bb + ((b_row + ntp * 16) * GSH + 16 * ks + b_colh) * 2);
                bf[2 * ntp][0] = r[0]; bf[2 * ntp][1] = r[1];
                bf[2 * ntp + 1][0] = r[2]; bf[2 * ntp + 1][1] = r[3];
            }
#pragma unroll
            for (int mt = 0; mt < 4; mt++)
#pragma unroll
                for (int nt = 0; nt < 4; nt++)
                    mma_f16(c[mt][nt], a[mt], bf[nt]);
        }
    }

#pragma unroll
    for (int mt = 0; mt < 4; mt++) {
        int row = bm + wm * 64 + mt * 16 + g;
#pragma unroll
        for (int nt = 0; nt < 4; nt++) {
            int col = bn + wn * 32 + nt * 8 + 2 * t;
            float bx = bias[col], by = bias[col + 1];
            *(float2*)&C[(size_t)row * KDIM + col] =
                make_float2(c[mt][nt][0] + bx, c[mt][nt][1] + by);
            *(float2*)&C[(size_t)(row + 8) * KDIM + col] =
                make_float2(c[mt][nt][2] + bx, c[mt][nt][3] + by);
        }
    }
}

// ---------------------------------------------------------------------------
// Flash attention (R11-exact, the 514.5us configuration): fp16 mma m16n8k16,
// 4-stage K/V cp.async pipeline, CTA = 128 q-rows, 8 warps x 16 q-rows.
// Q fragments hoisted; Q PRE-SCALED by 0.125*log2e (S in log2 domain).
// exp via ex2.approx.f16x2; warp-uniform corr-skip.
// ---------------------------------------------------------------------------
#define QSTR 72
#define KSTR 72
#define VSTR 72
#define QSZ  (128 * QSTR)              // halves
#define SSZ  (64 * KSTR + 64 * VSTR)   // halves per K/V stage

__global__ __launch_bounds__(256, 2) void attn_f16(
    const __half* __restrict__ Q, const __half* __restrict__ K,
    const __half* __restrict__ V, __half* __restrict__ O)
{
    extern __shared__ __half smh[];
    __half* Qs = smh;
    __half* KV = smh + QSZ;            // 4 stages of [K(64xKSTR) | V(64xVSTR)]
    const uint32_t Qs_b = (uint32_t)__cvta_generic_to_shared(Qs);
    const uint32_t KV_b = (uint32_t)__cvta_generic_to_shared(KV);

    const int tid  = threadIdx.x;
    const int lane = tid & 31;
    const int warp = tid >> 5;
    const int g = lane >> 2;
    const int t = lane & 3;
    const int wrow = warp * 16;

    const int qtile = blockIdx.x;
    const int bh = blockIdx.y;
    const int b = bh >> 4;
    const int h = bh & 15;
    const size_t rowbase = (size_t)b * T_;
    const int colbase = h * HDIM;

    const int lrow4 = tid >> 2;
    const int lcb4  = (tid & 3) * 16;

    auto fill_kv = [&](int kt, int s) {
        const size_t gb = (rowbase + kt * 64 + lrow4) * KDIM + colbase + lcb4;
        __half* kd = KV + s * SSZ + lrow4 * KSTR + lcb4;
        __half* vd = kd + 64 * KSTR;
        cp16(kd, K + gb); cp16(kd + 8, K + gb + 8);
        cp16(vd, V + gb); cp16(vd + 8, V + gb + 8);
    };

    // ---- Stage Q tile [128 x 64], then K/V tiles 0..2
    {
        const int qrow = tid >> 1;
        const int qcb  = (tid & 1) * 32;
        const __half* src = Q + (rowbase + qtile * 128 + qrow) * KDIM + colbase + qcb;
        __half* dst = Qs + qrow * QSTR + qcb;
        cp16(dst, src); cp16(dst + 8, src + 8);
        cp16(dst + 16, src + 16); cp16(dst + 24, src + 24);
        CP_COMMIT();
    }
    fill_kv(0, 0); CP_COMMIT();
    fill_kv(1, 1); CP_COMMIT();
    fill_kv(2, 2); CP_COMMIT();

    // ---- Hoist Q fragments (Q group done after wait 3)
    const int qa_row = wrow + (lane & 15);
    const int qa_colh = (lane >> 4) << 3;
    unsigned qf[4][4];
    CP_WAIT3();
    __syncthreads();
#pragma unroll
    for (int ds = 0; ds < 4; ds++)
        ldsm_x4(qf[ds], Qs_b + (qa_row * QSTR + 16 * ds + qa_colh) * 2);

    float m0 = -1e30f, m1 = -1e30f, l0 = 0.0f, l1 = 0.0f;
    float o[8][4];
#pragma unroll
    for (int j = 0; j < 8; j++)
#pragma unroll
        for (int e = 0; e < 4; e++) o[j][e] = 0.0f;

    const int kb_row = ((lane >> 4) << 3) + (lane & 7);
    const int kb_colh = ((lane >> 3) & 1) << 3;
    const int vb_row = (((lane >> 3) & 1) << 3) + (lane & 7);
    const int vb_colh = (lane >> 4) << 3;

    const int NT = T_ / 64;              // 32
    for (int kt = 0; kt < NT; kt++) {
        const int s = kt & 3;
        const uint32_t Kb = KV_b + s * SSZ * 2;
        const uint32_t Vb = Kb + 64 * KSTR * 2;

        CP_WAIT2();
        __syncthreads();
        const int jn = kt + 3;
        if (jn < NT) fill_kv(jn, jn & 3);
        CP_COMMIT();

        // ---- S = Q K^T (warp tile 16 x 64), S already in log2 domain
        float sc[8][4];
#pragma unroll
        for (int j = 0; j < 8; j++)
#pragma unroll
            for (int e = 0; e < 4; e++) sc[j][e] = 0.0f;

#pragma unroll
        for (int ds = 0; ds < 4; ds++) {
#pragma unroll
            for (int jj = 0; jj < 4; jj++) {
                unsigned r[4];
                ldsm_x4(r, Kb + ((16 * jj + kb_row) * KSTR + 16 * ds + kb_colh) * 2);
                mma_f16(sc[2 * jj], qf[ds], r);
                mma_f16(sc[2 * jj + 1], qf[ds], r + 2);
            }
        }

        // ---- Online softmax (rows g, g+8)
        float mx0 = -1e30f, mx1 = -1e30f;
#pragma unroll
        for (int j = 0; j < 8; j++) {
            mx0 = fmaxf(mx0, fmaxf(sc[j][0], sc[j][1]));
            mx1 = fmaxf(mx1, fmaxf(sc[j][2], sc[j][3]));
        }
        mx0 = fmaxf(mx0, __shfl_xor_sync(0xffffffffu, mx0, 1));
        mx0 = fmaxf(mx0, __shfl_xor_sync(0xffffffffu, mx0, 2));
        mx1 = fmaxf(mx1, __shfl_xor_sync(0xffffffffu, mx1, 1));
        mx1 = fmaxf(mx1, __shfl_xor_sync(0xffffffffu, mx1, 2));

        float mn0 = fmaxf(m0, mx0);
        float mn1 = fmaxf(m1, mx1);

        // P = exp2(S - m) via packed f16x2 MUFU; output is the mma fragment.
        unsigned pf[4][4];
        float rs0 = 0.0f, rs1 = 0.0f;
#pragma unroll
        for (int j = 0; j < 8; j++) {
            unsigned h01 = h2ex2(__floats2half2_rn(sc[j][0] - mn0, sc[j][1] - mn0));
            unsigned h23 = h2ex2(__floats2half2_rn(sc[j][2] - mn1, sc[j][3] - mn1));
            float2 f01 = __half22float2(*(__half2*)&h01);   // rounded values for l-sum
            float2 f23 = __half22float2(*(__half2*)&h23);
            rs0 += f01.x + f01.y;
            rs1 += f23.x + f23.y;
            pf[j >> 1][((j & 1) << 1) + 0] = h01;
            pf[j >> 1][((j & 1) << 1) + 1] = h23;
        }
        rs0 += __shfl_xor_sync(0xffffffffu, rs0, 1);
        rs0 += __shfl_xor_sync(0xffffffffu, rs0, 2);
        rs1 += __shfl_xor_sync(0xffffffffu, rs1, 1);
        rs1 += __shfl_xor_sync(0xffffffffu, rs1, 2);

        // Warp-uniform corr-skip: corr==1.0 exactly when max unchanged.
        bool nochange = (mn0 == m0) && (mn1 == m1);
        if (__all_sync(0xffffffffu, nochange)) {
            l0 += rs0;
            l1 += rs1;
        } else {
            float corr0 = ex2f(m0 - mn0);
            float corr1 = ex2f(m1 - mn1);
            l0 = l0 * corr0 + rs0;
            l1 = l1 * corr1 + rs1;
#pragma unroll
            for (int j = 0; j < 8; j++) {
                o[j][0] *= corr0; o[j][1] *= corr0;
                o[j][2] *= corr1; o[j][3] *= corr1;
            }
            m0 = mn0; m1 = mn1;
        }

        // ---- O += P V (V via ldmatrix.trans)
#pragma unroll
        for (int s2 = 0; s2 < 4; s2++) {
#pragma unroll
            for (int jj2 = 0; jj2 < 4; jj2++) {
                unsigned r[4];
                ldsm_x4_t(r, Vb + ((16 * s2 + vb_row) * VSTR + 16 * jj2 + vb_colh) * 2);
                mma_f16(o[2 * jj2], pf[s2], r);
                mma_f16(o[2 * jj2 + 1], pf[s2], r + 2);
            }
        }
    }

    // ---- Normalize, store fp16 ([b*t][h*64])
    float inv0 = 1.0f / l0;
    float inv1 = 1.0f / l1;
    size_t orow0 = (rowbase + qtile * 128 + wrow + g) * KDIM + colbase;
    size_t orow1 = orow0 + (size_t)8 * KDIM;
#pragma unroll
    for (int j = 0; j < 8; j++) {
        int col = 8 * j + 2 * t;
        *(__half2*)&O[orow0 + col] = __floats2half2_rn(o[j][0] * inv0, o[j][1] * inv0);
        *(__half2*)&O[orow1 + col] = __floats2half2_rn(o[j][2] * inv1, o[j][3] * inv1);
    }
}

// ---------------------------------------------------------------------------
// Launcher
// ---------------------------------------------------------------------------
extern "C" void kernel_launch(void* const* d_in, const int* in_sizes, int n_in,
                              void* d_out, int out_size)
{
    const float* x  = (const float*)d_in[0];
    const float* Wq = (const float*)d_in[1];
    const float* Wk = (const float*)d_in[2];
    const float* Wv = (const float*)d_in[3];
    const float* Wu = (const float*)d_in[4];
    const float* bu = (const float*)d_in[5];
    float* out = (float*)d_out;

    __half *q, *k, *v, *a;
    cudaGetSymbolAddress((void**)&q, g_q);
    cudaGetSymbolAddress((void**)&k, g_k);
    cudaGetSymbolAddress((void**)&v, g_v);
    cudaGetSymbolAddress((void**)&a, g_a);

    // Pre-pass: rounds x + weights, builds RoPE table (z=5)
    {
        int blocks_x = (ROWS * KDIM / 4 + 255) / 256;   // 8192 (covers all z)
        prepass<<<dim3(blocks_x, 1, 6), 256>>>(
            (const float4*)x, (const float4*)Wq, (const float4*)Wk,
            (const float4*)Wv, (const float4*)Wu);
    }

    cudaFuncSetAttribute(gemm_qkv, cudaFuncAttributeMaxDynamicSharedMemorySize, GSMEM);
    cudaFuncSetAttribute(gemm_out, cudaFuncAttributeMaxDynamicSharedMemorySize, GSMEM);

    // Fused QKV projections (one launch, grid.z selects Q/K/V)
    gemm_qkv<<<dim3(KDIM / 128, ROWS / 128, 3), 256, GSMEM>>>();

    // Attention: 128 q-rows per CTA, 8 warps x 16 rows (R11 geometry)
    const int attn_smem = (QSZ + 4 * SSZ) * (int)sizeof(__half);  // 92160 B
    cudaFuncSetAttribute(attn_f16, cudaFuncAttributeMaxDynamicSharedMemorySize, attn_smem);
    attn_f16<<<dim3(T_ / 128, B_ * HEADS), 256, attn_smem>>>(q, k, v, a);

    // Output projection + bias (fp32 store)
    gemm_out<<<dim3(KDIM / 128, ROWS / 128), 256, GSMEM>>>(bu, out);
}

// round 15
// speedup vs baseline: 1.0598x; 1.0247x over previous
#include <cuda_runtime.h>
#include <cuda_fp16.h>
#include <math.h>
#include <cstdint>

// Problem constants
#define B_      4
#define T_      2048
#define KDIM    1024
#define HEADS   16
#define HDIM    64
#define ROWS    (B_ * T_)          // 8192
#define HALF    (KDIM / 2)         // 512

// ---------------------------------------------------------------------------
// Scratch (device globals: allocation-free per harness rules)
// ---------------------------------------------------------------------------
__device__ __align__(16) __half g_q[ROWS * KDIM];
__device__ __align__(16) __half g_k[ROWS * KDIM];
__device__ __align__(16) __half g_v[ROWS * KDIM];
__device__ __align__(16) __half g_a[ROWS * KDIM];
__device__ __align__(16) __half g_xt[ROWS * KDIM];
__device__ __align__(16) __half g_wq[KDIM * KDIM];
__device__ __align__(16) __half g_wk[KDIM * KDIM];
__device__ __align__(16) __half g_wv[KDIM * KDIM];
__device__ __align__(16) __half g_wu[KDIM * KDIM];

// ---------------------------------------------------------------------------
// Helpers
// ---------------------------------------------------------------------------
__device__ __forceinline__ void mma_f16(float* c, const unsigned* a, const unsigned* b) {
    asm volatile(
        "mma.sync.aligned.m16n8k16.row.col.f32.f16.f16.f32 "
        "{%0,%1,%2,%3}, {%4,%5,%6,%7}, {%8,%9}, {%0,%1,%2,%3};\n"
        : "+f"(c[0]), "+f"(c[1]), "+f"(c[2]), "+f"(c[3])
        : "r"(a[0]), "r"(a[1]), "r"(a[2]), "r"(a[3]), "r"(b[0]), "r"(b[1]));
}

__device__ __forceinline__ void ldsm_x4(unsigned* r, uint32_t addr) {
    asm volatile("ldmatrix.sync.aligned.m8n8.x4.shared.b16 {%0,%1,%2,%3}, [%4];"
        : "=r"(r[0]), "=r"(r[1]), "=r"(r[2]), "=r"(r[3]) : "r"(addr));
}
__device__ __forceinline__ void ldsm_x4_t(unsigned* r, uint32_t addr) {
    asm volatile("ldmatrix.sync.aligned.m8n8.x4.trans.shared.b16 {%0,%1,%2,%3}, [%4];"
        : "=r"(r[0]), "=r"(r[1]), "=r"(r[2]), "=r"(r[3]) : "r"(addr));
}

__device__ __forceinline__ void cp16(void* dst_smem, const void* src) {
    unsigned d = (unsigned)__cvta_generic_to_shared(dst_smem);
    asm volatile("cp.async.cg.shared.global [%0], [%1], 16;\n" :: "r"(d), "l"(src));
}
#define CP_COMMIT() asm volatile("cp.async.commit_group;\n" ::: "memory")
#define CP_WAIT2()  asm volatile("cp.async.wait_group 2;\n" ::: "memory")
#define CP_WAIT3()  asm volatile("cp.async.wait_group 3;\n" ::: "memory")

__device__ __forceinline__ float ex2f(float x) {
    float y;
    asm("ex2.approx.f32 %0, %1;" : "=f"(y) : "f"(x));
    return y;
}
__device__ __forceinline__ unsigned h2ex2(__half2 x) {
    unsigned y;
    asm("ex2.approx.f16x2 %0, %1;" : "=r"(y) : "r"(*(unsigned*)&x));
    return y;
}

#define SOFTMAX_SCALE 0.1803368801111244f   // 0.125 * log2(e)

// ---------------------------------------------------------------------------
// Pre-pass (single launch): z=0 rounds x, z=1..4 round the four weights
// ---------------------------------------------------------------------------
__global__ void round_all(const float4* __restrict__ x,
                          const float4* __restrict__ Wq,
                          const float4* __restrict__ Wk,
                          const float4* __restrict__ Wv,
                          const float4* __restrict__ Wu)
{
    const int z = blockIdx.z;
    const float4* in;
    __half2* out;
    int n4;
    if (z == 0)      { in = x;  out = (__half2*)g_xt; n4 = ROWS * KDIM / 4; }
    else if (z == 1) { in = Wq; out = (__half2*)g_wq; n4 = KDIM * KDIM / 4; }
    else if (z == 2) { in = Wk; out = (__half2*)g_wk; n4 = KDIM * KDIM / 4; }
    else if (z == 3) { in = Wv; out = (__half2*)g_wv; n4 = KDIM * KDIM / 4; }
    else             { in = Wu; out = (__half2*)g_wu; n4 = KDIM * KDIM / 4; }
    int i = blockIdx.x * blockDim.x + threadIdx.x;
    if (i >= n4) return;
    float4 v = in[i];
    out[2 * i]     = __floats2half2_rn(v.x, v.y);
    out[2 * i + 1] = __floats2half2_rn(v.z, v.w);
}

// ---------------------------------------------------------------------------
// fp16 GEMM core: 128x128x32 CTA tile, 256 threads = 8 warps (2m x 4n),
// warp tile 64x32, 4-stage cp.async pipeline (wait_group 2),
// smem stride 40 halves (ldmatrix conflict-free).
// ---------------------------------------------------------------------------
#define GSH 40
#define GSTGH (2 * 128 * GSH)          // halves per stage (A+B)
#define GSTGB (GSTGH * 2)              // bytes per stage (20480)
#define GSMEM (4 * GSTGB)              // 81920 B

// Fused QKV projection: grid (8, 64, 3).  z selects weight/output/RoPE.
// RoPE inline (trig hidden under epilogue stores); z==0 (Q) pre-scaled.
__global__ __launch_bounds__(256, 2) void gemm_qkv()
{
    extern __shared__ __half smh[];
    const uint32_t base_b = (uint32_t)__cvta_generic_to_shared(smh);

    const int z = blockIdx.z;
    const __half* A = g_xt;
    const __half* B = (z == 0) ? g_wq : (z == 1) ? g_wk : g_wv;
    __half* C = (z == 0) ? g_q : (z == 1) ? g_k : g_v;
    const bool do_rope = (z < 2);

    const int tid  = threadIdx.x;
    const int lane = tid & 31;
    const int warp = tid >> 5;
    const int g = lane >> 2;
    const int t = lane & 3;
    const int wm = warp >> 2;
    const int wn = warp & 3;
    const int bm = blockIdx.y * 128;
    const int bn = blockIdx.x * 128;

    float c[4][4][4];
#pragma unroll
    for (int i = 0; i < 4; i++)
#pragma unroll
        for (int j = 0; j < 4; j++)
#pragma unroll
            for (int e = 0; e < 4; e++) c[i][j][e] = 0.0f;

    const int lrow = tid >> 1;
    const int lcb  = (tid & 1) * 16;
    const __half* Ap = A + (size_t)(bm + lrow) * KDIM + lcb;
    const __half* Bp = B + (size_t)(bn + lrow) * KDIM + lcb;

    auto fill = [&](int ch, int s) {
        __half* Asd = smh + s * GSTGH + lrow * GSH + lcb;
        __half* Bsd = Asd + 128 * GSH;
        cp16(Asd, Ap + ch * 32); cp16(Asd + 8, Ap + ch * 32 + 8);
        cp16(Bsd, Bp + ch * 32); cp16(Bsd + 8, Bp + ch * 32 + 8);
    };

    fill(0, 0); CP_COMMIT();
    fill(1, 1); CP_COMMIT();
    fill(2, 2); CP_COMMIT();

    const int a_row = wm * 64 + (lane & 15);
    const int a_colh = (lane >> 4) << 3;
    const int b_row = wn * 32 + ((lane >> 4) << 3) + (lane & 7);
    const int b_colh = ((lane >> 3) & 1) << 3;

    const int NCH = KDIM / 32;           // 32
    for (int i = 0; i < NCH; i++) {
        const int s = i & 3;
        CP_WAIT2();
        __syncthreads();
        const int j = i + 3;
        if (j < NCH) fill(j, j & 3);
        CP_COMMIT();

        const uint32_t Ab = base_b + s * GSTGB;
        const uint32_t Bb = Ab + 128 * GSH * 2;
#pragma unroll
        for (int ks = 0; ks < 2; ks++) {
            unsigned a[4][4], bf[4][2];
#pragma unroll
            for (int mt = 0; mt < 4; mt++)
                ldsm_x4(a[mt], Ab + ((a_row + mt * 16) * GSH + 16 * ks + a_colh) * 2);
#pragma unroll
            for (int ntp = 0; ntp < 2; ntp++) {
                unsigned r[4];
                ldsm_x4(r, Bb + ((b_row + ntp * 16) * GSH + 16 * ks + b_colh) * 2);
                bf[2 * ntp][0] = r[0]; bf[2 * ntp][1] = r[1];
                bf[2 * ntp + 1][0] = r[2]; bf[2 * ntp + 1][1] = r[3];
            }
#pragma unroll
            for (int mt = 0; mt < 4; mt++)
#pragma unroll
                for (int nt = 0; nt < 4; nt++)
                    mma_f16(c[mt][nt], a[mt], bf[nt]);
        }
    }

    // Epilogue: inline RoPE (z<2), Q pre-scaled; fp16 store
#pragma unroll
    for (int mt = 0; mt < 4; mt++) {
        int row = bm + wm * 64 + mt * 16 + g;
#pragma unroll
        for (int nt = 0; nt < 4; nt++) {
            int col = bn + wn * 32 + nt * 8 + 2 * t;
            float v0x = c[mt][nt][0], v0y = c[mt][nt][1];
            float v1x = c[mt][nt][2], v1y = c[mt][nt][3];
            if (do_rope) {
                int j = col >> 1;
                float theta = powf(10000.0f, -(float)j * (1.0f / (float)HALF));
                int t0 = row & (T_ - 1);
                float s0, c0; sincosf((float)t0 * theta, &s0, &c0);
                float s1, c1; sincosf((float)(t0 + 8) * theta, &s1, &c1);
                float r0x = v0x * c0 - v0y * s0;
                float r0y = v0x * s0 + v0y * c0;
                float r1x = v1x * c1 - v1y * s1;
                float r1y = v1x * s1 + v1y * c1;
                v0x = r0x; v0y = r0y; v1x = r1x; v1y = r1y;
                if (z == 0) {
                    v0x *= SOFTMAX_SCALE; v0y *= SOFTMAX_SCALE;
                    v1x *= SOFTMAX_SCALE; v1y *= SOFTMAX_SCALE;
                }
            }
            *(__half2*)&C[(size_t)row * KDIM + col] = __floats2half2_rn(v0x, v0y);
            *(__half2*)&C[(size_t)(row + 8) * KDIM + col] = __floats2half2_rn(v1x, v1y);
        }
    }
}

// Output projection: fp32 store + bias
__global__ __launch_bounds__(256, 2) void gemm_out(
    const float* __restrict__ bias, float* __restrict__ C)
{
    extern __shared__ __half smh[];
    const uint32_t base_b = (uint32_t)__cvta_generic_to_shared(smh);

    const int tid  = threadIdx.x;
    const int lane = tid & 31;
    const int warp = tid >> 5;
    const int g = lane >> 2;
    const int t = lane & 3;
    const int wm = warp >> 2;
    const int wn = warp & 3;
    const int bm = blockIdx.y * 128;
    const int bn = blockIdx.x * 128;

    float c[4][4][4];
#pragma unroll
    for (int i = 0; i < 4; i++)
#pragma unroll
        for (int j = 0; j < 4; j++)
#pragma unroll
            for (int e = 0; e < 4; e++) c[i][j][e] = 0.0f;

    const int lrow = tid >> 1;
    const int lcb  = (tid & 1) * 16;
    const __half* Ap = g_a  + (size_t)(bm + lrow) * KDIM + lcb;
    const __half* Bp = g_wu + (size_t)(bn + lrow) * KDIM + lcb;

    auto fill = [&](int ch, int s) {
        __half* Asd = smh + s * GSTGH + lrow * GSH + lcb;
        __half* Bsd = Asd + 128 * GSH;
        cp16(Asd, Ap + ch * 32); cp16(Asd + 8, Ap + ch * 32 + 8);
        cp16(Bsd, Bp + ch * 32); cp16(Bsd + 8, Bp + ch * 32 + 8);
    };

    fill(0, 0); CP_COMMIT();
    fill(1, 1); CP_COMMIT();
    fill(2, 2); CP_COMMIT();

    const int a_row = wm * 64 + (lane & 15);
    const int a_colh = (lane >> 4) << 3;
    const int b_row = wn * 32 + ((lane >> 4) << 3) + (lane & 7);
    const int b_colh = ((lane >> 3) & 1) << 3;

    const int NCH = KDIM / 32;
    for (int i = 0; i < NCH; i++) {
        const int s = i & 3;
        CP_WAIT2();
        __syncthreads();
        const int j = i + 3;
        if (j < NCH) fill(j, j & 3);
        CP_COMMIT();

        const uint32_t Ab = base_b + s * GSTGB;
        const uint32_t Bb = Ab + 128 * GSH * 2;
#pragma unroll
        for (int ks = 0; ks < 2; ks++) {
            unsigned a[4][4], bf[4][2];
#pragma unroll
            for (int mt = 0; mt < 4; mt++)
                ldsm_x4(a[mt], Ab + ((a_row + mt * 16) * GSH + 16 * ks + a_colh) * 2);
#pragma unroll
            for (int ntp = 0; ntp < 2; ntp++) {
                unsigned r[4];
                ldsm_x4(r, Bb + ((b_row + ntp * 16) * GSH + 16 * ks + b_colh) * 2);
                bf[2 * ntp][0] = r[0]; bf[2 * ntp][1] = r[1];
                bf[2 * ntp + 1][0] = r[2]; bf[2 * ntp + 1][1] = r[3];
            }
#pragma unroll
            for (int mt = 0; mt < 4; mt++)
#pragma unroll
                for (int nt = 0; nt < 4; nt++)
                    mma_f16(c[mt][nt], a[mt], bf[nt]);
        }
    }

#pragma unroll
    for (int mt = 0; mt < 4; mt++) {
        int row = bm + wm * 64 + mt * 16 + g;
#pragma unroll
        for (int nt = 0; nt < 4; nt++) {
            int col = bn + wn * 32 + nt * 8 + 2 * t;
            float bx = bias[col], by = bias[col + 1];
            *(float2*)&C[(size_t)row * KDIM + col] =
                make_float2(c[mt][nt][0] + bx, c[mt][nt][1] + by);
            *(float2*)&C[(size_t)(row + 8) * KDIM + col] =
                make_float2(c[mt][nt][2] + bx, c[mt][nt][3] + by);
        }
    }
}

// ---------------------------------------------------------------------------
// Flash attention, fp16 mma m16n8k16.  CTA = 128 q-rows, 8 warps x 16 rows.
// *** Deferred-PV software pipeline ***: iteration i issues S_i, then
// PV_{i-1} (P frags from prev iter, register-resident), then softmax_i.
// The softmax MUFU/SHFL chain no longer sits between the two mma bursts.
// 5-stage K/V cp.async ring with prefetch depth 3 so the prefetch target
// never collides with V_{i-1} (still being read) or K_i.
// Q hoisted; Q pre-scaled by 0.125*log2e; ex2.approx.f16x2 P; corr-skip.
// ---------------------------------------------------------------------------
#define QSTR 72
#define KSTR 72
#define VSTR 72
#define QSZ  (128 * QSTR)              // halves (18432 B)
#define SSZ  (64 * KSTR + 64 * VSTR)   // halves per K/V stage (18432 B)
#define NSTGA 5

__global__ __launch_bounds__(256, 2) void attn_f16(
    const __half* __restrict__ Q, const __half* __restrict__ K,
    const __half* __restrict__ V, __half* __restrict__ O)
{
    extern __shared__ __half smh[];
    __half* Qs = smh;
    __half* KV = smh + QSZ;            // 5 stages of [K(64xKSTR) | V(64xVSTR)]
    const uint32_t Qs_b = (uint32_t)__cvta_generic_to_shared(Qs);
    const uint32_t KV_b = (uint32_t)__cvta_generic_to_shared(KV);

    const int tid  = threadIdx.x;
    const int lane = tid & 31;
    const int warp = tid >> 5;
    const int g = lane >> 2;
    const int t = lane & 3;
    const int wrow = warp * 16;

    const int qtile = blockIdx.x;
    const int bh = blockIdx.y;
    const int b = bh >> 4;
    const int h = bh & 15;
    const size_t rowbase = (size_t)b * T_;
    const int colbase = h * HDIM;

    const int lrow4 = tid >> 2;
    const int lcb4  = (tid & 3) * 16;

    auto fill_kv = [&](int kt, int s) {
        const size_t gb = (rowbase + kt * 64 + lrow4) * KDIM + colbase + lcb4;
        __half* kd = KV + s * SSZ + lrow4 * KSTR + lcb4;
        __half* vd = kd + 64 * KSTR;
        cp16(kd, K + gb); cp16(kd + 8, K + gb + 8);
        cp16(vd, V + gb); cp16(vd + 8, V + gb + 8);
    };

    // ---- Stage Q tile [128 x 64], then K/V tiles 0..2 (stages 0..2)
    {
        const int qrow = tid >> 1;
        const int qcb  = (tid & 1) * 32;
        const __half* src = Q + (rowbase + qtile * 128 + qrow) * KDIM + colbase + qcb;
        __half* dst = Qs + qrow * QSTR + qcb;
        cp16(dst, src); cp16(dst + 8, src + 8);
        cp16(dst + 16, src + 16); cp16(dst + 24, src + 24);
        CP_COMMIT();
    }
    fill_kv(0, 0); CP_COMMIT();
    fill_kv(1, 1); CP_COMMIT();
    fill_kv(2, 2); CP_COMMIT();

    // ---- Hoist Q fragments (Q group done after wait 3)
    const int qa_row = wrow + (lane & 15);
    const int qa_colh = (lane >> 4) << 3;
    unsigned qf[4][4];
    CP_WAIT3();
    __syncthreads();
#pragma unroll
    for (int ds = 0; ds < 4; ds++)
        ldsm_x4(qf[ds], Qs_b + (qa_row * QSTR + 16 * ds + qa_colh) * 2);

    float m0 = -1e30f, m1 = -1e30f, l0 = 0.0f, l1 = 0.0f;
    float o[8][4];
#pragma unroll
    for (int j = 0; j < 8; j++)
#pragma unroll
        for (int e = 0; e < 4; e++) o[j][e] = 0.0f;

    const int kb_row = ((lane >> 4) << 3) + (lane & 7);
    const int kb_colh = ((lane >> 3) & 1) << 3;
    const int vb_row = (((lane >> 3) & 1) << 3) + (lane & 7);
    const int vb_colh = (lane >> 4) << 3;

    unsigned pfp[4][4];                  // P of previous tile
    uint32_t Vb_prev = 0;

    int s_cur = 0, s_pre = 3;
    const int NT = T_ / 64;              // 32
    for (int kt = 0; kt < NT; kt++) {
        const uint32_t Kb = KV_b + s_cur * SSZ * 2;
        const uint32_t Vb = Kb + 64 * KSTR * 2;

        CP_WAIT2();                      // chunk kt resident
        __syncthreads();                 // all warps done with stage s_pre's last use
        const int jn = kt + 3;
        if (jn < NT) fill_kv(jn, s_pre);
        CP_COMMIT();

        // ---- S = Q K^T (warp tile 16 x 64), S already in log2 domain
        float sc[8][4];
#pragma unroll
        for (int j = 0; j < 8; j++)
#pragma unroll
            for (int e = 0; e < 4; e++) sc[j][e] = 0.0f;

#pragma unroll
        for (int ds = 0; ds < 4; ds++) {
#pragma unroll
            for (int jj = 0; jj < 4; jj++) {
                unsigned r[4];
                ldsm_x4(r, Kb + ((16 * jj + kb_row) * KSTR + 16 * ds + kb_colh) * 2);
                mma_f16(sc[2 * jj], qf[ds], r);
                mma_f16(sc[2 * jj + 1], qf[ds], r + 2);
            }
        }

        // ---- Deferred PV: O += P_{kt-1} V_{kt-1}  (independent of S_kt)
        if (kt > 0) {
#pragma unroll
            for (int s2 = 0; s2 < 4; s2++) {
#pragma unroll
                for (int jj2 = 0; jj2 < 4; jj2++) {
                    unsigned r[4];
                    ldsm_x4_t(r, Vb_prev + ((16 * s2 + vb_row) * VSTR + 16 * jj2 + vb_colh) * 2);
                    mma_f16(o[2 * jj2], pfp[s2], r);
                    mma_f16(o[2 * jj2 + 1], pfp[s2], r + 2);
                }
            }
        }

        // ---- Online softmax for tile kt (rows g, g+8); writes pfp
        float mx0 = -1e30f, mx1 = -1e30f;
#pragma unroll
        for (int j = 0; j < 8; j++) {
            mx0 = fmaxf(mx0, fmaxf(sc[j][0], sc[j][1]));
            mx1 = fmaxf(mx1, fmaxf(sc[j][2], sc[j][3]));
        }
        mx0 = fmaxf(mx0, __shfl_xor_sync(0xffffffffu, mx0, 1));
        mx0 = fmaxf(mx0, __shfl_xor_sync(0xffffffffu, mx0, 2));
        mx1 = fmaxf(mx1, __shfl_xor_sync(0xffffffffu, mx1, 1));
        mx1 = fmaxf(mx1, __shfl_xor_sync(0xffffffffu, mx1, 2));

        float mn0 = fmaxf(m0, mx0);
        float mn1 = fmaxf(m1, mx1);

        float rs0 = 0.0f, rs1 = 0.0f;
#pragma unroll
        for (int j = 0; j < 8; j++) {
            unsigned h01 = h2ex2(__floats2half2_rn(sc[j][0] - mn0, sc[j][1] - mn0));
            unsigned h23 = h2ex2(__floats2half2_rn(sc[j][2] - mn1, sc[j][3] - mn1));
            float2 f01 = __half22float2(*(__half2*)&h01);
            float2 f23 = __half22float2(*(__half2*)&h23);
            rs0 += f01.x + f01.y;
            rs1 += f23.x + f23.y;
            pfp[j >> 1][((j & 1) << 1) + 0] = h01;
            pfp[j >> 1][((j & 1) << 1) + 1] = h23;
        }
        rs0 += __shfl_xor_sync(0xffffffffu, rs0, 1);
        rs0 += __shfl_xor_sync(0xffffffffu, rs0, 2);
        rs1 += __shfl_xor_sync(0xffffffffu, rs1, 1);
        rs1 += __shfl_xor_sync(0xffffffffu, rs1, 2);

        // Warp-uniform corr-skip (corr==1.0 exactly when max unchanged).
        // Rescale of o happens AFTER PV_{kt-1} was accumulated -> same math.
        bool nochange = (mn0 == m0) && (mn1 == m1);
        if (__all_sync(0xffffffffu, nochange)) {
            l0 += rs0;
            l1 += rs1;
        } else {
            float corr0 = ex2f(m0 - mn0);
            float corr1 = ex2f(m1 - mn1);
            l0 = l0 * corr0 + rs0;
            l1 = l1 * corr1 + rs1;
#pragma unroll
            for (int j = 0; j < 8; j++) {
                o[j][0] *= corr0; o[j][1] *= corr0;
                o[j][2] *= corr1; o[j][3] *= corr1;
            }
            m0 = mn0; m1 = mn1;
        }

        Vb_prev = Vb;
        s_cur = (s_cur + 1 == NSTGA) ? 0 : s_cur + 1;
        s_pre = (s_pre + 1 == NSTGA) ? 0 : s_pre + 1;
    }

    // ---- Final PV for the last tile
#pragma unroll
    for (int s2 = 0; s2 < 4; s2++) {
#pragma unroll
        for (int jj2 = 0; jj2 < 4; jj2++) {
            unsigned r[4];
            ldsm_x4_t(r, Vb_prev + ((16 * s2 + vb_row) * VSTR + 16 * jj2 + vb_colh) * 2);
            mma_f16(o[2 * jj2], pfp[s2], r);
            mma_f16(o[2 * jj2 + 1], pfp[s2], r + 2);
        }
    }

    // ---- Normalize, store fp16 ([b*t][h*64])
    float inv0 = 1.0f / l0;
    float inv1 = 1.0f / l1;
    size_t orow0 = (rowbase + qtile * 128 + wrow + g) * KDIM + colbase;
    size_t orow1 = orow0 + (size_t)8 * KDIM;
#pragma unroll
    for (int j = 0; j < 8; j++) {
        int col = 8 * j + 2 * t;
        *(__half2*)&O[orow0 + col] = __floats2half2_rn(o[j][0] * inv0, o[j][1] * inv0);
        *(__half2*)&O[orow1 + col] = __floats2half2_rn(o[j][2] * inv1, o[j][3] * inv1);
    }
}

// ---------------------------------------------------------------------------
// Launcher
// ---------------------------------------------------------------------------
extern "C" void kernel_launch(void* const* d_in, const int* in_sizes, int n_in,
                              void* d_out, int out_size)
{
    const float* x  = (const float*)d_in[0];
    const float* Wq = (const float*)d_in[1];
    const float* Wk = (const float*)d_in[2];
    const float* Wv = (const float*)d_in[3];
    const float* Wu = (const float*)d_in[4];
    const float* bu = (const float*)d_in[5];
    float* out = (float*)d_out;

    __half *q, *k, *v, *a;
    cudaGetSymbolAddress((void**)&q, g_q);
    cudaGetSymbolAddress((void**)&k, g_k);
    cudaGetSymbolAddress((void**)&v, g_v);
    cudaGetSymbolAddress((void**)&a, g_a);

    // Pre-pass: one launch rounds x + all 4 weights to fp16
    {
        int blocks_x = (ROWS * KDIM / 4 + 255) / 256;   // 8192
        round_all<<<dim3(blocks_x, 1, 5), 256>>>(
            (const float4*)x, (const float4*)Wq, (const float4*)Wk,
            (const float4*)Wv, (const float4*)Wu);
    }

    cudaFuncSetAttribute(gemm_qkv, cudaFuncAttributeMaxDynamicSharedMemorySize, GSMEM);
    cudaFuncSetAttribute(gemm_out, cudaFuncAttributeMaxDynamicSharedMemorySize, GSMEM);

    // Fused QKV projections (one launch, grid.z selects Q/K/V)
    gemm_qkv<<<dim3(KDIM / 128, ROWS / 128, 3), 256, GSMEM>>>();

    // Attention: 128 q-rows per CTA, 8 warps, 5-stage deferred-PV pipeline
    const int attn_smem = (QSZ + NSTGA * SSZ) * (int)sizeof(__half);  // 110592 B
    cudaFuncSetAttribute(attn_f16, cudaFuncAttributeMaxDynamicSharedMemorySize, attn_smem);
    attn_f16<<<dim3(T_ / 128, B_ * HEADS), 256, attn_smem>>>(q, k, v, a);

    // Output projection + bias (fp32 store)
    gemm_out<<<dim3(KDIM / 128, ROWS / 128), 256, GSMEM>>>(bu, out);
}